// round 4
// baseline (speedup 1.0000x reference)
#include <cuda_runtime.h>
#include <cuda_bf16.h>
#include <cstddef>
#include <cstdint>

// Problem constants
#define BATCH 4
#define SEQ   2048
#define DIM   1024
#define HEADS 16
#define DH    64
#define MROWS (BATCH*SEQ)  // 8192
#define SCALE 0.03125f     // 1/sqrt(1024)

// Scratch (allocation-free rule: __device__ globals)
__device__ float g_Q[(size_t)MROWS * DIM];
__device__ float g_K[(size_t)MROWS * DIM];
__device__ float g_V[(size_t)MROWS * DIM];
__device__ float g_C[(size_t)MROWS * DIM];

// ---------------------------------------------------------------------------
// TF32 mma GEMM: C[M,N] = A[M,K] * B[K,N], row-major, fp32 in/out.
// 128x128x16 block tile, 256 threads (8 warps, 4x2), warp tile 32x64.
// mma.sync.aligned.m16n8k8 tf32, cvt.rna at SMEM store time.
// ---------------------------------------------------------------------------
#define BM 128
#define BN 128
#define BK 16
#define SA_STR 20    // [m][k] stride: conflict-free fragment loads
#define SB_STR 136   // [k][n] stride: conflict-free fragment loads

__device__ __forceinline__ float to_tf32(float x) {
    float r;
    asm("cvt.rna.tf32.f32 %0, %1;" : "=f"(r) : "f"(x));
    return r;
}

__device__ __forceinline__ void mma_tf32(float* c, const uint32_t* a, const uint32_t* b) {
    asm volatile(
        "mma.sync.aligned.m16n8k8.row.col.f32.tf32.tf32.f32 "
        "{%0,%1,%2,%3}, {%4,%5,%6,%7}, {%8,%9}, {%0,%1,%2,%3};"
        : "+f"(c[0]), "+f"(c[1]), "+f"(c[2]), "+f"(c[3])
        : "r"(a[0]), "r"(a[1]), "r"(a[2]), "r"(a[3]), "r"(b[0]), "r"(b[1]));
}

__global__ __launch_bounds__(256) void gemm_tf32(const float* __restrict__ A,
                                                 const float* __restrict__ B,
                                                 float* __restrict__ C,
                                                 int M, int N, int K) {
    __shared__ float sA[BM * SA_STR];   // [m][k], stride 20
    __shared__ float sB[BK * SB_STR];   // [k][n], stride 136

    int tid  = threadIdx.x;
    int lane = tid & 31;
    int warp = tid >> 5;
    int gr = lane >> 2;        // 0..7
    int tq = lane & 3;         // 0..3
    int wm = (warp & 3) * 32;  // warp M offset
    int wn = (warp >> 2) * 64; // warp N offset

    int bx = blockIdx.x, by = blockIdx.y;

    // Global load mapping (per BK-tile):
    // A tile 128x16 = 512 float4: idx i -> row=i>>2, kcol=(i&3)*4; i = tid, tid+256
    // B tile 16x128 = 512 float4: idx i -> krow=i>>5, ncol=(i&31)*4; i = tid, tid+256
    int a_row1 = tid >> 2;
    int a_kc   = (tid & 3) * 4;
    int b_kr   = tid >> 5;           // 0..7
    int b_nc   = (tid & 31) * 4;

    const float* Ap = A + (size_t)(by * BM + a_row1) * K + a_kc;
    const float* Bp = B + (size_t)b_kr * N + bx * BN + b_nc;

    float acc[2][8][4];
#pragma unroll
    for (int mt = 0; mt < 2; mt++)
#pragma unroll
        for (int nt = 0; nt < 8; nt++)
#pragma unroll
            for (int i = 0; i < 4; i++) acc[mt][nt][i] = 0.f;

    // Prefetch first tile
    float4 ra0 = *(const float4*)(Ap);
    float4 ra1 = *(const float4*)(Ap + (size_t)64 * K);
    float4 rb0 = *(const float4*)(Bp);
    float4 rb1 = *(const float4*)(Bp + (size_t)8 * N);

    for (int k0 = 0; k0 < K; k0 += BK) {
        __syncthreads();
        // Store (with tf32 rounding) to SMEM
        {
            float4 t;
            t.x = to_tf32(ra0.x); t.y = to_tf32(ra0.y); t.z = to_tf32(ra0.z); t.w = to_tf32(ra0.w);
            *(float4*)&sA[a_row1 * SA_STR + a_kc] = t;
            t.x = to_tf32(ra1.x); t.y = to_tf32(ra1.y); t.z = to_tf32(ra1.z); t.w = to_tf32(ra1.w);
            *(float4*)&sA[(a_row1 + 64) * SA_STR + a_kc] = t;
            t.x = to_tf32(rb0.x); t.y = to_tf32(rb0.y); t.z = to_tf32(rb0.z); t.w = to_tf32(rb0.w);
            *(float4*)&sB[b_kr * SB_STR + b_nc] = t;
            t.x = to_tf32(rb1.x); t.y = to_tf32(rb1.y); t.z = to_tf32(rb1.z); t.w = to_tf32(rb1.w);
            *(float4*)&sB[(b_kr + 8) * SB_STR + b_nc] = t;
        }
        __syncthreads();

        // Prefetch next tile (overlaps with mma below)
        if (k0 + BK < K) {
            Ap += BK;
            Bp += (size_t)BK * N;
            ra0 = *(const float4*)(Ap);
            ra1 = *(const float4*)(Ap + (size_t)64 * K);
            rb0 = *(const float4*)(Bp);
            rb1 = *(const float4*)(Bp + (size_t)8 * N);
        }

#pragma unroll
        for (int kt = 0; kt < BK; kt += 8) {
            uint32_t af[2][4];
            uint32_t bf[8][2];
#pragma unroll
            for (int mt = 0; mt < 2; mt++) {
                int base = (wm + mt * 16 + gr) * SA_STR + kt + tq;
                af[mt][0] = __float_as_uint(sA[base]);
                af[mt][1] = __float_as_uint(sA[base + 8 * SA_STR]);
                af[mt][2] = __float_as_uint(sA[base + 4]);
                af[mt][3] = __float_as_uint(sA[base + 8 * SA_STR + 4]);
            }
#pragma unroll
            for (int nt = 0; nt < 8; nt++) {
                int nb = wn + nt * 8 + gr;
                bf[nt][0] = __float_as_uint(sB[(kt + tq) * SB_STR + nb]);
                bf[nt][1] = __float_as_uint(sB[(kt + tq + 4) * SB_STR + nb]);
            }
#pragma unroll
            for (int mt = 0; mt < 2; mt++)
#pragma unroll
                for (int nt = 0; nt < 8; nt++)
                    mma_tf32(acc[mt][nt], af[mt], bf[nt]);
        }
    }

    // Epilogue: c0,c1 contiguous cols -> float2 stores
#pragma unroll
    for (int mt = 0; mt < 2; mt++) {
#pragma unroll
        for (int nt = 0; nt < 8; nt++) {
            int row = by * BM + wm + mt * 16 + gr;
            int col = bx * BN + wn + nt * 8 + 2 * tq;
            *(float2*)&C[(size_t)row * N + col] =
                make_float2(acc[mt][nt][0], acc[mt][nt][1]);
            *(float2*)&C[(size_t)(row + 8) * N + col] =
                make_float2(acc[mt][nt][2], acc[mt][nt][3]);
        }
    }
}

// ---------------------------------------------------------------------------
// Flash attention, 4 threads per query row (16 head-dims each).
// 256 threads/block = 64 queries. Dot product via shfl_xor over the quad.
// grid = (SEQ/64, HEADS, BATCH).
// ---------------------------------------------------------------------------
#define KT 16
#define DSPLIT 4
#define DPART (DH / DSPLIT)   // 16

__global__ __launch_bounds__(256) void attn_kernel(const float* __restrict__ Q,
                                                   const float* __restrict__ K,
                                                   const float* __restrict__ V,
                                                   float* __restrict__ O) {
    __shared__ float sK[KT][DH];
    __shared__ float sV[KT][DH];

    int b = blockIdx.z;
    int h = blockIdx.y;
    int t = threadIdx.x;
    int qi   = t >> 2;          // 0..63 query within block
    int part = t & 3;           // 0..3
    int d0   = part * DPART;    // 0,16,32,48
    int qrow = blockIdx.x * 64 + qi;

    const float* qp = Q + ((size_t)(b * SEQ + qrow)) * DIM + h * DH + d0;
    float q[DPART], o[DPART];
#pragma unroll
    for (int i = 0; i < DPART / 4; i++) {
        float4 v4 = ((const float4*)qp)[i];
        q[4*i+0] = v4.x; q[4*i+1] = v4.y; q[4*i+2] = v4.z; q[4*i+3] = v4.w;
    }
#pragma unroll
    for (int d = 0; d < DPART; d++) o[d] = 0.f;

    float m = -1e30f, l = 0.f;
    const size_t kbase = (size_t)b * SEQ * DIM + (size_t)h * DH;

    // staging map: 256 float4 per tile (KT*DH/4), one per thread
    int sr  = t >> 4;            // 0..15 row
    int sc4 = t & 15;            // 0..15 float4 col

    for (int k0 = 0; k0 < SEQ; k0 += KT) {
        size_t rowoff = kbase + (size_t)(k0 + sr) * DIM;
        float4 kk = *((const float4*)(K + rowoff) + sc4);
        float4 vv = *((const float4*)(V + rowoff) + sc4);
        __syncthreads();
        ((float4*)&sK[sr][0])[sc4] = kk;
        ((float4*)&sV[sr][0])[sc4] = vv;
        __syncthreads();

        float s[KT];
        float mx = m;
#pragma unroll
        for (int k = 0; k < KT; k++) {
            float p = 0.f;
#pragma unroll
            for (int d = 0; d < DPART; d++) p += q[d] * sK[k][d0 + d];
            p += __shfl_xor_sync(0xffffffffu, p, 1);
            p += __shfl_xor_sync(0xffffffffu, p, 2);
            s[k] = p * SCALE;
            mx = fmaxf(mx, s[k]);
        }

        float corr = __expf(m - mx);
        m = mx;
        l *= corr;
#pragma unroll
        for (int d = 0; d < DPART; d++) o[d] *= corr;

#pragma unroll
        for (int k = 0; k < KT; k++) {
            float p = __expf(s[k] - m);
            l += p;
#pragma unroll
            for (int d = 0; d < DPART; d++) o[d] += p * sV[k][d0 + d];
        }
    }

    float inv = 1.f / l;
    float* op = O + ((size_t)(b * SEQ + qrow)) * DIM + h * DH + d0;
#pragma unroll
    for (int i = 0; i < DPART / 4; i++) {
        ((float4*)op)[i] = make_float4(o[4*i+0]*inv, o[4*i+1]*inv,
                                       o[4*i+2]*inv, o[4*i+3]*inv);
    }
}

// ---------------------------------------------------------------------------
extern "C" void kernel_launch(void* const* d_in, const int* in_sizes, int n_in,
                              void* d_out, int out_size) {
    const float* x  = (const float*)d_in[0];
    const float* WQ = (const float*)d_in[1];
    const float* WK = (const float*)d_in[2];
    const float* WV = (const float*)d_in[3];
    const float* WO = (const float*)d_in[4];
    float* out = (float*)d_out;

    float *pQ, *pK, *pV, *pC;
    cudaGetSymbolAddress((void**)&pQ, g_Q);
    cudaGetSymbolAddress((void**)&pK, g_K);
    cudaGetSymbolAddress((void**)&pV, g_V);
    cudaGetSymbolAddress((void**)&pC, g_C);

    dim3 ggrid(DIM / BN, MROWS / BM);     // (8, 64)
    gemm_tf32<<<ggrid, 256>>>(x, WQ, pQ, MROWS, DIM, DIM);
    gemm_tf32<<<ggrid, 256>>>(x, WK, pK, MROWS, DIM, DIM);
    gemm_tf32<<<ggrid, 256>>>(x, WV, pV, MROWS, DIM, DIM);

    dim3 agrid(SEQ / 64, HEADS, BATCH);   // (32, 16, 4)
    attn_kernel<<<agrid, 256>>>(pQ, pK, pV, pC);

    gemm_tf32<<<ggrid, 256>>>(pC, WO, out, MROWS, DIM, DIM);
}

// round 6
// speedup vs baseline: 2.1323x; 2.1323x over previous
#include <cuda_runtime.h>
#include <cuda_bf16.h>
#include <cstddef>
#include <cstdint>

// Problem constants
#define BATCH 4
#define SEQ   2048
#define DIM   1024
#define HEADS 16
#define DH    64
#define MROWS (BATCH*SEQ)  // 8192
#define SCALE 0.03125f     // 1/sqrt(1024)

// Scratch (allocation-free rule: __device__ globals)
__device__ float g_Q[(size_t)MROWS * DIM];
__device__ float g_K[(size_t)MROWS * DIM];
__device__ float g_V[(size_t)MROWS * DIM];
__device__ float g_C[(size_t)MROWS * DIM];

// ---------------------------------------------------------------------------
// TF32 mma.sync GEMM: C[M,N] = A[M,K] * B[K,N], row-major, fp32 in/out.
// 128x128x16 block tile, 256 threads (8 warps, 4x2), warp tile 32x64.
// (tcgen05 is unavailable: harness compiles PTX at .target sm_103, not sm_103a)
// ---------------------------------------------------------------------------
#define BM 128
#define BN 128
#define BK 16
#define SA_STR 20    // [m][k] stride: conflict-free fragment loads
#define SB_STR 136   // [k][n] stride: conflict-free fragment loads

__device__ __forceinline__ float to_tf32(float x) {
    float r;
    asm("cvt.rna.tf32.f32 %0, %1;" : "=f"(r) : "f"(x));
    return r;
}

__device__ __forceinline__ void mma_tf32(float* c, const uint32_t* a, const uint32_t* b) {
    asm volatile(
        "mma.sync.aligned.m16n8k8.row.col.f32.tf32.tf32.f32 "
        "{%0,%1,%2,%3}, {%4,%5,%6,%7}, {%8,%9}, {%0,%1,%2,%3};"
        : "+f"(c[0]), "+f"(c[1]), "+f"(c[2]), "+f"(c[3])
        : "r"(a[0]), "r"(a[1]), "r"(a[2]), "r"(a[3]), "r"(b[0]), "r"(b[1]));
}

__global__ __launch_bounds__(256) void gemm_tf32(const float* __restrict__ A,
                                                 const float* __restrict__ B,
                                                 float* __restrict__ C,
                                                 int M, int N, int K) {
    __shared__ float sA[BM * SA_STR];   // [m][k], stride 20
    __shared__ float sB[BK * SB_STR];   // [k][n], stride 136

    int tid  = threadIdx.x;
    int lane = tid & 31;
    int warp = tid >> 5;
    int gr = lane >> 2;        // 0..7
    int tq = lane & 3;         // 0..3
    int wm = (warp & 3) * 32;  // warp M offset
    int wn = (warp >> 2) * 64; // warp N offset

    int bx = blockIdx.x, by = blockIdx.y;

    int a_row1 = tid >> 2;
    int a_kc   = (tid & 3) * 4;
    int b_kr   = tid >> 5;           // 0..7
    int b_nc   = (tid & 31) * 4;

    const float* Ap = A + (size_t)(by * BM + a_row1) * K + a_kc;
    const float* Bp = B + (size_t)b_kr * N + bx * BN + b_nc;

    float acc[2][8][4];
#pragma unroll
    for (int mt = 0; mt < 2; mt++)
#pragma unroll
        for (int nt = 0; nt < 8; nt++)
#pragma unroll
            for (int i = 0; i < 4; i++) acc[mt][nt][i] = 0.f;

    // Prefetch first tile
    float4 ra0 = *(const float4*)(Ap);
    float4 ra1 = *(const float4*)(Ap + (size_t)64 * K);
    float4 rb0 = *(const float4*)(Bp);
    float4 rb1 = *(const float4*)(Bp + (size_t)8 * N);

    for (int k0 = 0; k0 < K; k0 += BK) {
        __syncthreads();
        {
            float4 t;
            t.x = to_tf32(ra0.x); t.y = to_tf32(ra0.y); t.z = to_tf32(ra0.z); t.w = to_tf32(ra0.w);
            *(float4*)&sA[a_row1 * SA_STR + a_kc] = t;
            t.x = to_tf32(ra1.x); t.y = to_tf32(ra1.y); t.z = to_tf32(ra1.z); t.w = to_tf32(ra1.w);
            *(float4*)&sA[(a_row1 + 64) * SA_STR + a_kc] = t;
            t.x = to_tf32(rb0.x); t.y = to_tf32(rb0.y); t.z = to_tf32(rb0.z); t.w = to_tf32(rb0.w);
            *(float4*)&sB[b_kr * SB_STR + b_nc] = t;
            t.x = to_tf32(rb1.x); t.y = to_tf32(rb1.y); t.z = to_tf32(rb1.z); t.w = to_tf32(rb1.w);
            *(float4*)&sB[(b_kr + 8) * SB_STR + b_nc] = t;
        }
        __syncthreads();

        if (k0 + BK < K) {
            Ap += BK;
            Bp += (size_t)BK * N;
            ra0 = *(const float4*)(Ap);
            ra1 = *(const float4*)(Ap + (size_t)64 * K);
            rb0 = *(const float4*)(Bp);
            rb1 = *(const float4*)(Bp + (size_t)8 * N);
        }

#pragma unroll
        for (int kt = 0; kt < BK; kt += 8) {
            uint32_t af[2][4];
            uint32_t bf[8][2];
#pragma unroll
            for (int mt = 0; mt < 2; mt++) {
                int base = (wm + mt * 16 + gr) * SA_STR + kt + tq;
                af[mt][0] = __float_as_uint(sA[base]);
                af[mt][1] = __float_as_uint(sA[base + 8 * SA_STR]);
                af[mt][2] = __float_as_uint(sA[base + 4]);
                af[mt][3] = __float_as_uint(sA[base + 8 * SA_STR + 4]);
            }
#pragma unroll
            for (int nt = 0; nt < 8; nt++) {
                int nb = wn + nt * 8 + gr;
                bf[nt][0] = __float_as_uint(sB[(kt + tq) * SB_STR + nb]);
                bf[nt][1] = __float_as_uint(sB[(kt + tq + 4) * SB_STR + nb]);
            }
#pragma unroll
            for (int mt = 0; mt < 2; mt++)
#pragma unroll
                for (int nt = 0; nt < 8; nt++)
                    mma_tf32(acc[mt][nt], af[mt], bf[nt]);
        }
    }

#pragma unroll
    for (int mt = 0; mt < 2; mt++) {
#pragma unroll
        for (int nt = 0; nt < 8; nt++) {
            int row = by * BM + wm + mt * 16 + gr;
            int col = bx * BN + wn + nt * 8 + 2 * tq;
            *(float2*)&C[(size_t)row * N + col] =
                make_float2(acc[mt][nt][0], acc[mt][nt][1]);
            *(float2*)&C[(size_t)(row + 8) * N + col] =
                make_float2(acc[mt][nt][2], acc[mt][nt][3]);
        }
    }
}

// ---------------------------------------------------------------------------
// Flash attention (round-2 version, measured-good): one thread = one query.
// grid = (SEQ/128, HEADS, BATCH), block = 128.
// ---------------------------------------------------------------------------
#define KT 16

__global__ __launch_bounds__(128) void attn_kernel(const float* __restrict__ Q,
                                                   const float* __restrict__ K,
                                                   const float* __restrict__ V,
                                                   float* __restrict__ O) {
    __shared__ float sK[KT][DH];
    __shared__ float sV[KT][DH];

    int b = blockIdx.z;
    int h = blockIdx.y;
    int t = threadIdx.x;
    int qrow = blockIdx.x * 128 + t;

    const float* qp = Q + ((size_t)(b * SEQ + qrow)) * DIM + h * DH;
    float q[DH], o[DH];
#pragma unroll
    for (int i = 0; i < DH / 4; i++) {
        float4 v4 = ((const float4*)qp)[i];
        q[4 * i + 0] = v4.x; q[4 * i + 1] = v4.y;
        q[4 * i + 2] = v4.z; q[4 * i + 3] = v4.w;
    }
#pragma unroll
    for (int d = 0; d < DH; d++) o[d] = 0.f;

    float m = -1e30f, l = 0.f;
    const size_t kbase = (size_t)b * SEQ * DIM + (size_t)h * DH;

    for (int k0 = 0; k0 < SEQ; k0 += KT) {
#pragma unroll
        for (int i = 0; i < 2; i++) {
            int slot = t + i * 128;          // 0..255
            int r  = slot >> 4;              // 0..15
            int c4 = slot & 15;              // 0..15
            size_t rowoff = kbase + (size_t)(k0 + r) * DIM;
            ((float4*)&sK[r][0])[c4] = *((const float4*)(K + rowoff) + c4);
            ((float4*)&sV[r][0])[c4] = *((const float4*)(V + rowoff) + c4);
        }
        __syncthreads();

        float s[KT];
        float mx = m;
#pragma unroll
        for (int k = 0; k < KT; k++) {
            float acc = 0.f;
#pragma unroll
            for (int d = 0; d < DH; d++) acc += q[d] * sK[k][d];
            s[k] = acc * SCALE;
            mx = fmaxf(mx, s[k]);
        }

        float corr = __expf(m - mx);
        m = mx;
        l *= corr;
#pragma unroll
        for (int d = 0; d < DH; d++) o[d] *= corr;

#pragma unroll
        for (int k = 0; k < KT; k++) {
            float p = __expf(s[k] - m);
            l += p;
#pragma unroll
            for (int d = 0; d < DH; d++) o[d] += p * sV[k][d];
        }
        __syncthreads();
    }

    float inv = 1.f / l;
    float* op = O + ((size_t)(b * SEQ + qrow)) * DIM + h * DH;
#pragma unroll
    for (int i = 0; i < DH / 4; i++) {
        ((float4*)op)[i] = make_float4(o[4 * i + 0] * inv, o[4 * i + 1] * inv,
                                       o[4 * i + 2] * inv, o[4 * i + 3] * inv);
    }
}

// ---------------------------------------------------------------------------
extern "C" void kernel_launch(void* const* d_in, const int* in_sizes, int n_in,
                              void* d_out, int out_size) {
    const float* x  = (const float*)d_in[0];
    const float* WQ = (const float*)d_in[1];
    const float* WK = (const float*)d_in[2];
    const float* WV = (const float*)d_in[3];
    const float* WO = (const float*)d_in[4];
    float* out = (float*)d_out;

    float *pQ, *pK, *pV, *pC;
    cudaGetSymbolAddress((void**)&pQ, g_Q);
    cudaGetSymbolAddress((void**)&pK, g_K);
    cudaGetSymbolAddress((void**)&pV, g_V);
    cudaGetSymbolAddress((void**)&pC, g_C);

    dim3 ggrid(DIM / BN, MROWS / BM);     // (8, 64)
    gemm_tf32<<<ggrid, 256>>>(x, WQ, pQ, MROWS, DIM, DIM);
    gemm_tf32<<<ggrid, 256>>>(x, WK, pK, MROWS, DIM, DIM);
    gemm_tf32<<<ggrid, 256>>>(x, WV, pV, MROWS, DIM, DIM);

    dim3 agrid(SEQ / 128, HEADS, BATCH);  // (16, 16, 4)
    attn_kernel<<<agrid, 128>>>(pQ, pK, pV, pC);

    gemm_tf32<<<ggrid, 256>>>(pC, WO, out, MROWS, DIM, DIM);
}